// round 11
// baseline (speedup 1.0000x reference)
#include <cuda_runtime.h>
#include <cuda_bf16.h>
#include <cstdint>

#define BATCH   16
#define C_DIM   256
#define N_ROWS  16384
#define K_CB    8192
#define Z_ELEMS 4194304
#define OUT_LOSS_OFF 4194304
#define OUT_IDX_OFF  4194305

#define CAP       32
#define MARGIN_EZ 2e-4f
#define CHUNKS    64            // 256 int8 = 64 packed int32 per row

#define TM        112           // rows per screen block (16 strips x 7 rows)
#define NTH       256           // screen threads (16 x 16) -> 8 warps, balanced SMSPs
#define NRB       147           // row blocks
#define NBLK      (NRB * 2)     // x2 K-halves

// ---- static device scratch ----
__device__ __align__(16) int   g_qzT[CHUNKS][N_ROWS];   // z int8, chunk-major
__device__ __align__(16) int   g_cbT[CHUNKS][K_CB];     // codebook int8, chunk-major
__device__ __align__(16) float g_zrow[N_ROWS * C_DIM];  // z fp32, row-major
__device__ float  g_z2[N_ROWS];
__device__ float  g_szinv[N_ROWS];   // 127/max|z_row|
__device__ float  g_e2[K_CB];
__device__ float  g_se[K_CB];        // max|e_k|/127
__device__ float  g_seinv[K_CB];     // 127/max|e_k|
__device__ int    g_cnt[N_ROWS];
__device__ int    g_cand[N_ROWS * CAP];
__device__ int    g_bestidx[N_ROWS];
__device__ double g_losspart[4096];

__device__ __forceinline__ unsigned fkey(float f) {
    unsigned u = __float_as_uint(f);
    return (u & 0x80000000u) ? ~u : (u | 0x80000000u);
}
__device__ __forceinline__ float fdec(unsigned k) {
    unsigned u = (k & 0x80000000u) ? (k & 0x7fffffffu) : ~k;
    return __uint_as_float(u);
}
__device__ __forceinline__ uint32_t smem_u32(const void* p) {
    uint32_t a;
    asm("{ .reg .u64 t; cvta.to.shared.u64 t, %1; cvt.u32.u64 %0, t; }" : "=r"(a) : "l"(p));
    return a;
}
__device__ __forceinline__ int q8(float v, float inv) {
    int q = __float2int_rn(v * inv);
    q = max(-127, min(127, q));
    return q & 255;
}
#define CP_ASYNC16(dst, src) \
    asm volatile("cp.async.cg.shared.global [%0],[%1],16;\n" :: "r"(dst), "l"(src))
#define CP_COMMIT() asm volatile("cp.async.commit_group;\n")
#define CP_WAIT0()  asm volatile("cp.async.wait_group 0;\n")

// ---------------------------------------------------------------------------
// rowstat_z: coalesced load; z2 bit-identical to R1; emits g_zrow AND the
// quantized chunk-major g_qzT (fused — z is read exactly once); zeroes g_cnt.
// ---------------------------------------------------------------------------
__global__ __launch_bounds__(256) void rowstat_z_kernel(const float* __restrict__ z) {
    __shared__ float sm[256 * 33];
    __shared__ float sh_inv[32];
    const int n0 = blockIdx.x * 32;
    const int b = n0 >> 10;
    const int r0 = n0 & 1023;
    const int lane = threadIdx.x & 31;
    const int w = threadIdx.x >> 5;

    for (int c = w; c < 256; c += 8)
        sm[c * 33 + lane] = z[(size_t)b * 262144 + (size_t)c * 1024 + r0 + lane];
    __syncthreads();

#pragma unroll
    for (int q = 0; q < 4; ++q) {
        const int rr = w + q * 8;
        float s = 0.0f, mx = 0.0f;
#pragma unroll
        for (int t = 0; t < 8; ++t) {
            float v = sm[(lane + 32 * t) * 33 + rr];
            s = fmaf(v, v, s);
            mx = fmaxf(mx, fabsf(v));
            g_zrow[(size_t)(n0 + rr) * 256 + lane + 32 * t] = v;
        }
#pragma unroll
        for (int o = 16; o > 0; o >>= 1) {
            s += __shfl_xor_sync(0xffffffffu, s, o);
            mx = fmaxf(mx, __shfl_xor_sync(0xffffffffu, mx, o));
        }
        if (lane == 0) {
            g_z2[n0 + rr] = s;
            float inv = 127.0f / fmaxf(mx, 1e-20f);
            g_szinv[n0 + rr] = inv;
            sh_inv[rr] = inv;
            g_cnt[n0 + rr] = 0;
        }
    }
    __syncthreads();

    // fused quantize: 32 rows x 64 chunks
#pragma unroll
    for (int i = 0; i < 8; ++i) {
        int sidx = threadIdx.x + 256 * i;      // 0..2047
        int rr = sidx & 31, cc = sidx >> 5;
        float inv = sh_inv[rr];
        int wq = q8(sm[(4 * cc + 0) * 33 + rr], inv)
               | (q8(sm[(4 * cc + 1) * 33 + rr], inv) << 8)
               | (q8(sm[(4 * cc + 2) * 33 + rr], inv) << 16)
               | (q8(sm[(4 * cc + 3) * 33 + rr], inv) << 24);
        g_qzT[cc][n0 + rr] = wq;               // consecutive rr -> coalesced
    }
}

__global__ void rowstat_e_kernel(const float* __restrict__ cb) {
    int warp = (blockIdx.x * blockDim.x + threadIdx.x) >> 5;
    int lane = threadIdx.x & 31;
    if (warp >= K_CB) return;
    const float* p = cb + (size_t)warp * C_DIM;
    float s = 0.0f, mx = 0.0f;
#pragma unroll
    for (int t = 0; t < 8; ++t) {
        float v = p[lane + 32 * t];
        s = fmaf(v, v, s);
        mx = fmaxf(mx, fabsf(v));
    }
#pragma unroll
    for (int o = 16; o > 0; o >>= 1) {
        s += __shfl_xor_sync(0xffffffffu, s, o);
        mx = fmaxf(mx, __shfl_xor_sync(0xffffffffu, mx, o));
    }
    if (lane == 0) {
        g_e2[warp] = s;
        mx = fmaxf(mx, 1e-20f);
        g_se[warp]    = mx * (1.0f / 127.0f);
        g_seinv[warp] = 127.0f / mx;
    }
}

__global__ void quant_cb_kernel(const float* __restrict__ cb) {
    int t = blockIdx.x * 256 + threadIdx.x;
    int cc = t >> 13;
    int k  = t & 8191;
    float4 v = *(const float4*)(cb + (size_t)k * 256 + cc * 4);
    float inv = g_seinv[k];
    int w = q8(v.x, inv) | (q8(v.y, inv) << 8) |
            (q8(v.z, inv) << 16) | (q8(v.w, inv) << 24);
    g_cbT[cc][k] = w;
}

// ---------------------------------------------------------------------------
// DP4A screen, split-K: block = (row-block, K-half). 112 rows x 4096 cands
// (32 tiles of 128). 256 threads (8 warps, SMSP-balanced), 7x8 microtile.
// Per-half margin screen (sound: winner's half-max >= winner); lists merged
// into g_cand via atomicAdd reservation; total-count overflow -> full rescan.
// ---------------------------------------------------------------------------
#define A_BYTES    (CHUNKS * 128 * 4)        // 32768 (padded: 16 strips x 8)
#define BBUF_BYTES (CHUNKS * 128 * 4)        // 32768
#define SE_BYTES   512u
#define DYN_SM     (A_BYTES + 2u * BBUF_BYTES + 2u * SE_BYTES)  // 99328

__global__ __launch_bounds__(NTH, 1) void screen_dp4a_kernel() {
    extern __shared__ char dsm[];
    int*   As = (int*)dsm;                                    // [64][128] padded
    int*   Bs = (int*)(dsm + A_BYTES);                        // [2][64][128]
    float* Se = (float*)(dsm + A_BYTES + 2u * BBUF_BYTES);    // [2][128]
    __shared__ unsigned s_rowmax[TM];
    __shared__ int s_cnt[TM];
    __shared__ int s_base[TM];
    __shared__ int s_list[TM * CAP];

    const int tid = threadIdx.x;
    const int tx = tid & 15;       // 16 candidate strips
    const int ty = tid >> 4;       // 16 row strips (7 rows each)
    const int kb   = blockIdx.x & 1;        // K half
    const int row0 = (blockIdx.x >> 1) * TM;
    const int t0 = kb * 32, t1 = t0 + 32;
    const unsigned smu = smem_u32(dsm);

    for (int i = tid; i < TM; i += NTH) { s_cnt[i] = 0; s_rowmax[i] = 0u; }

    float margin_u[7];
#pragma unroll
    for (int i = 0; i < 7; ++i)
        margin_u[i] = MARGIN_EZ * g_szinv[min(row0 + ty * 7 + i, N_ROWS - 1)];

    // ---- B[t0] + Se[t0] via cp.async (aligned) ----
    {
        const int k0 = t0 * 128;
        for (int s = tid; s < CHUNKS * 32; s += NTH) {
            int cc = s & 63, u = s >> 6;
            CP_ASYNC16(smu + A_BYTES + (cc * 128 + u * 4) * 4, &g_cbT[cc][k0 + u * 4]);
        }
        if (tid < 32) CP_ASYNC16(smu + A_BYTES + 2u * BBUF_BYTES + tid * 16,
                                 (const char*)(g_se + k0) + tid * 16);
        CP_COMMIT();
    }

    // ---- A preload via plain loads (once per block) ----
    for (int s = tid; s < CHUNKS * TM; s += NTH) {
        int cc = s & 63, lr = s >> 6;
        int strip = lr / 7, rr = lr - strip * 7;
        As[cc * 128 + strip * 8 + rr] = g_qzT[cc][min(row0 + lr, N_ROWS - 1)];
    }

    for (int t = t0; t < t1; ++t) {
        CP_WAIT0();
        __syncthreads();   // publishes plain A stores (first iter) and B[t]

        if (t + 1 < t1) {
            const int k1 = (t + 1) * 128;
            const int b1 = (t + 1) & 1;
            unsigned dst = smu + A_BYTES + (unsigned)b1 * BBUF_BYTES;
            for (int s = tid; s < CHUNKS * 32; s += NTH) {
                int cc = s & 63, u = s >> 6;
                CP_ASYNC16(dst + (cc * 128 + u * 4) * 4, &g_cbT[cc][k1 + u * 4]);
            }
            if (tid < 32)
                CP_ASYNC16(smu + A_BYTES + 2u * BBUF_BYTES + (unsigned)b1 * SE_BYTES + tid * 16,
                           (const char*)(g_se + k1) + tid * 16);
            CP_COMMIT();
        }

        const int*   Bt = Bs + (t & 1) * (BBUF_BYTES / 4);
        const float* St = Se + (t & 1) * 128;
        int acc[7][8];
#pragma unroll
        for (int i = 0; i < 7; ++i)
#pragma unroll
            for (int j = 0; j < 8; ++j) acc[i][j] = 0;

#pragma unroll 4
        for (int cc = 0; cc < CHUNKS; ++cc) {
            int a[8], b[8];
            *(int4*)&a[0] = *(const int4*)&As[cc * 128 + ty * 8];
            *(int4*)&a[4] = *(const int4*)&As[cc * 128 + ty * 8 + 4];   // a[7] = pad
            *(int4*)&b[0] = *(const int4*)&Bt[cc * 128 + tx * 4];
            *(int4*)&b[4] = *(const int4*)&Bt[cc * 128 + 64 + tx * 4];
#pragma unroll
            for (int i = 0; i < 7; ++i)
#pragma unroll
                for (int j = 0; j < 8; ++j)
                    acc[i][j] = __dp4a(a[i], b[j], acc[i][j]);
        }

        float sev[8];
#pragma unroll
        for (int j = 0; j < 4; ++j) {
            sev[j]     = St[tx * 4 + j];
            sev[j + 4] = St[64 + tx * 4 + j];
        }

#pragma unroll
        for (int i = 0; i < 7; ++i) {
            float m = -3.4e38f;
#pragma unroll
            for (int j = 0; j < 8; ++j) m = fmaxf(m, sev[j] * (float)acc[i][j]);
            atomicMax(&s_rowmax[ty * 7 + i], fkey(m));
        }
#pragma unroll
        for (int i = 0; i < 7; ++i) {
            const int r = ty * 7 + i;
            const float th = fdec(s_rowmax[r]) - margin_u[i];
#pragma unroll
            for (int j = 0; j < 8; ++j) {
                float v = sev[j] * (float)acc[i][j];
                if (v > th) {
                    int k = t * 128 + ((j < 4) ? (tx * 4 + j) : (64 + tx * 4 + j - 4));
                    int slot = atomicAdd(&s_cnt[r], 1);
                    if (slot < CAP) s_list[r * CAP + slot] = k;
                }
            }
        }
    }
    __syncthreads();

    // merge into global lists (order-independent final result)
    for (int r = tid; r < TM; r += NTH)
        if (row0 + r < N_ROWS)
            s_base[r] = atomicAdd(&g_cnt[row0 + r], s_cnt[r]);
    __syncthreads();
    for (int i = tid; i < TM * CAP; i += NTH) {
        int r = i >> 5, sl = i & 31;
        if (row0 + r < N_ROWS && sl < min(s_cnt[r], CAP)) {
            int dst = s_base[r] + sl;
            if (dst < CAP) g_cand[(row0 + r) * CAP + dst] = s_list[i];
        }
    }
}

// ---------------------------------------------------------------------------
// exact recheck (validated): smem-staged candidates, bit-identical dot
// ---------------------------------------------------------------------------
__global__ __launch_bounds__(32) void recheck_kernel(const float* __restrict__ cb)
{
    __shared__ float srows[256 * 33];
    __shared__ float zs[256];
    const int n = blockIdx.x;
    const int lane = threadIdx.x;

    {
        const float4* zr4 = (const float4*)(g_zrow + (size_t)n * 256);
        float4* zs4 = (float4*)zs;
        zs4[lane] = zr4[lane];
        zs4[lane + 32] = zr4[lane + 32];
    }
    __syncwarp();

    const float z2v = g_z2[n];
    const int cnt = g_cnt[n];
    unsigned long long key = ~0ull;

    if (cnt <= CAP) {
        const int myk = g_cand[n * CAP + min(lane, cnt - 1)];
        const int sub  = lane >> 3;
        const int ch   = lane & 7;
        for (int kk0 = 0; kk0 < cnt; kk0 += 4) {
            const int kk = kk0 + sub;
            const int kb2 = __shfl_sync(0xffffffffu, myk, min(kk, cnt - 1));
            const float4* cr4 = (const float4*)(cb + (size_t)kb2 * 256);
            const bool act = (kk < cnt);
#pragma unroll
            for (int u = 0; u < 8; ++u) {
                float4 v = cr4[ch + 8 * u];
                if (act) {
                    const int c = (ch + 8 * u) * 4;
                    srows[(c + 0) * 33 + kk] = v.x;
                    srows[(c + 1) * 33 + kk] = v.y;
                    srows[(c + 2) * 33 + kk] = v.z;
                    srows[(c + 3) * 33 + kk] = v.w;
                }
            }
        }
        __syncwarp();
        if (lane < cnt) {
            float a = 0.0f;
#pragma unroll 8
            for (int c = 0; c < 256; ++c)
                a = fmaf(zs[c], srows[c * 33 + lane], a);
            float d = (z2v + g_e2[myk]) - 2.0f * a;
            key = ((unsigned long long)__float_as_uint(d) << 32) | (unsigned)myk;
        }
    } else {
        for (int k = lane; k < K_CB; k += 32) {
            const float* cr = cb + (size_t)k * 256;
            float a = 0.0f;
#pragma unroll 16
            for (int c = 0; c < 256; ++c) a = fmaf(zs[c], cr[c], a);
            float d = (z2v + g_e2[k]) - 2.0f * a;
            unsigned long long kk = ((unsigned long long)__float_as_uint(d) << 32) | (unsigned)k;
            key = (kk < key) ? kk : key;
        }
    }
#pragma unroll
    for (int o = 16; o > 0; o >>= 1) {
        unsigned long long ok = __shfl_xor_sync(0xffffffffu, key, o);
        key = (ok < key) ? ok : key;
    }
    if (lane == 0) g_bestidx[n] = (int)(unsigned)(key & 0xffffffffu);
}

// ---------------------------------------------------------------------------
// epilogue: zp from g_zrow (contiguous quad -> float4 coalesced)
// ---------------------------------------------------------------------------
__global__ void epilogue_kernel(const float* __restrict__ cb,
                                float* __restrict__ out, int out_size)
{
    int q = blockIdx.x * 256 + threadIdx.x;
    int t = q * 4;
    int c2 = t & 255;
    int w2 = (t >> 8) & 31;
    int h2 = (t >> 13) & 31;
    int b  = t >> 18;
    int n = b * 1024 + w2 * 32 + (c2 >> 3);           // scrambled gather index
    int cbase = (c2 & 7) * 32 + h2;
    const float* cr = cb + (size_t)g_bestidx[n] * C_DIM + cbase;
    float4 v;
    v.x = cr[0]; v.y = cr[32]; v.z = cr[64]; v.w = cr[96];
    float4 zv = *(const float4*)(g_zrow + (size_t)(b * 1024 + h2 * 32 + w2) * 256 + c2);
    float d0 = zv.x - v.x;
    float d1 = zv.y - v.y;
    float d2 = zv.z - v.z;
    float d3 = zv.w - v.w;
    *(float4*)(out + t) = v;
    float diff2 = d0 * d0 + d1 * d1 + d2 * d2 + d3 * d3;

    __shared__ double sred[256];
    sred[threadIdx.x] = (double)diff2;
    __syncthreads();
#pragma unroll
    for (int s = 128; s > 0; s >>= 1) {
        if (threadIdx.x < s) sred[threadIdx.x] += sred[threadIdx.x + s];
        __syncthreads();
    }
    if (threadIdx.x == 0) g_losspart[blockIdx.x] = sred[0];
}

__global__ void finalize_kernel(float* __restrict__ out, int out_size)
{
    __shared__ double sred[256];
    double s = 0.0;
    for (int i = threadIdx.x; i < 4096; i += 256) s += g_losspart[i];
    sred[threadIdx.x] = s;
    __syncthreads();
#pragma unroll
    for (int st = 128; st > 0; st >>= 1) {
        if (threadIdx.x < st) sred[threadIdx.x] += sred[threadIdx.x + st];
        __syncthreads();
    }
    if (threadIdx.x == 0) {
        double m = sred[0] / (double)Z_ELEMS;
        float loss = (float)(m + 0.25 * m);
        if (OUT_LOSS_OFF < out_size) out[OUT_LOSS_OFF] = loss;
    }
    for (int i = threadIdx.x; i < N_ROWS; i += 256) {
        int o = OUT_IDX_OFF + i;
        if (o < out_size) out[o] = (float)g_bestidx[i];
    }
}

extern "C" void kernel_launch(void* const* d_in, const int* in_sizes, int n_in,
                              void* d_out, int out_size)
{
    const float* z  = (const float*)d_in[0];
    const float* cb = (const float*)d_in[1];
    float* out = (float*)d_out;

    cudaFuncSetAttribute(screen_dp4a_kernel,
                         cudaFuncAttributeMaxDynamicSharedMemorySize, DYN_SM);

    rowstat_z_kernel<<<512, 256>>>(z);
    rowstat_e_kernel<<<(K_CB * 32) / 256, 256>>>(cb);
    quant_cb_kernel<<<(CHUNKS * K_CB) / 256, 256>>>(cb);
    screen_dp4a_kernel<<<NBLK, NTH, DYN_SM>>>();
    recheck_kernel<<<N_ROWS, 32>>>(cb);
    epilogue_kernel<<<Z_ELEMS / 1024, 256>>>(cb, out, out_size);
    finalize_kernel<<<1, 256>>>(out, out_size);
}

// round 12
// speedup vs baseline: 3.3875x; 3.3875x over previous
#include <cuda_runtime.h>
#include <cuda_bf16.h>
#include <cstdint>

#define BATCH   16
#define C_DIM   256
#define N_ROWS  16384
#define K_CB    8192
#define Z_ELEMS 4194304
#define OUT_LOSS_OFF 4194304
#define OUT_IDX_OFF  4194305

#define CAP       32
#define MARGIN_EZ 2e-4f
#define CHUNKS    64            // 256 int8 = 64 packed int32 per row

#define TM        112           // rows per screen block (16 strips x 7 rows)
#define NTH       256           // screen threads (16 x 16) -> 8 warps, balanced SMSPs
#define NBLK      147           // ceil(16384/112)

// ---- static device scratch ----
__device__ __align__(16) int   g_qzT[CHUNKS][N_ROWS];   // z int8, chunk-major
__device__ __align__(16) int   g_cbT[CHUNKS][K_CB];     // codebook int8, chunk-major
__device__ __align__(16) float g_zrow[N_ROWS * C_DIM];  // z fp32, row-major
__device__ float  g_z2[N_ROWS];
__device__ float  g_szinv[N_ROWS];   // 127/max|z_row|
__device__ float  g_e2[K_CB];
__device__ float  g_se[K_CB];        // max|e_k|/127
__device__ float  g_seinv[K_CB];     // 127/max|e_k|
__device__ int    g_cnt[N_ROWS];
__device__ int    g_cand[N_ROWS * CAP];
__device__ int    g_bestidx[N_ROWS];
__device__ double g_losspart[4096];

__device__ __forceinline__ unsigned fkey(float f) {
    unsigned u = __float_as_uint(f);
    return (u & 0x80000000u) ? ~u : (u | 0x80000000u);
}
__device__ __forceinline__ float fdec(unsigned k) {
    unsigned u = (k & 0x80000000u) ? (k & 0x7fffffffu) : ~k;
    return __uint_as_float(u);
}
__device__ __forceinline__ uint32_t smem_u32(const void* p) {
    uint32_t a;
    asm("{ .reg .u64 t; cvta.to.shared.u64 t, %1; cvt.u32.u64 %0, t; }" : "=r"(a) : "l"(p));
    return a;
}
__device__ __forceinline__ int q8(float v, float inv) {
    int q = __float2int_rn(v * inv);
    q = max(-127, min(127, q));
    return q & 255;
}
#define CP_ASYNC16(dst, src) \
    asm volatile("cp.async.cg.shared.global [%0],[%1],16;\n" :: "r"(dst), "l"(src))
#define CP_COMMIT() asm volatile("cp.async.commit_group;\n")
#define CP_WAIT0()  asm volatile("cp.async.wait_group 0;\n")

// ---------------------------------------------------------------------------
// rowstat_z: coalesced load; z2 bit-identical to R1; emits g_zrow AND the
// quantized chunk-major g_qzT (fused — z is read exactly once).
// ---------------------------------------------------------------------------
__global__ __launch_bounds__(256) void rowstat_z_kernel(const float* __restrict__ z) {
    __shared__ float sm[256 * 33];
    __shared__ float sh_inv[32];
    const int n0 = blockIdx.x * 32;
    const int b = n0 >> 10;
    const int r0 = n0 & 1023;
    const int lane = threadIdx.x & 31;
    const int w = threadIdx.x >> 5;

    for (int c = w; c < 256; c += 8)
        sm[c * 33 + lane] = z[(size_t)b * 262144 + (size_t)c * 1024 + r0 + lane];
    __syncthreads();

#pragma unroll
    for (int q = 0; q < 4; ++q) {
        const int rr = w + q * 8;
        float s = 0.0f, mx = 0.0f;
#pragma unroll
        for (int t = 0; t < 8; ++t) {
            float v = sm[(lane + 32 * t) * 33 + rr];
            s = fmaf(v, v, s);
            mx = fmaxf(mx, fabsf(v));
            g_zrow[(size_t)(n0 + rr) * 256 + lane + 32 * t] = v;
        }
#pragma unroll
        for (int o = 16; o > 0; o >>= 1) {
            s += __shfl_xor_sync(0xffffffffu, s, o);
            mx = fmaxf(mx, __shfl_xor_sync(0xffffffffu, mx, o));
        }
        if (lane == 0) {
            g_z2[n0 + rr] = s;
            float inv = 127.0f / fmaxf(mx, 1e-20f);
            g_szinv[n0 + rr] = inv;
            sh_inv[rr] = inv;
        }
    }
    __syncthreads();

    // fused quantize: 32 rows x 64 chunks
#pragma unroll
    for (int i = 0; i < 8; ++i) {
        int sidx = threadIdx.x + 256 * i;      // 0..2047
        int rr = sidx & 31, cc = sidx >> 5;
        float inv = sh_inv[rr];
        int wq = q8(sm[(4 * cc + 0) * 33 + rr], inv)
               | (q8(sm[(4 * cc + 1) * 33 + rr], inv) << 8)
               | (q8(sm[(4 * cc + 2) * 33 + rr], inv) << 16)
               | (q8(sm[(4 * cc + 3) * 33 + rr], inv) << 24);
        g_qzT[cc][n0 + rr] = wq;               // consecutive rr -> coalesced
    }
}

__global__ void rowstat_e_kernel(const float* __restrict__ cb) {
    int warp = (blockIdx.x * blockDim.x + threadIdx.x) >> 5;
    int lane = threadIdx.x & 31;
    if (warp >= K_CB) return;
    const float* p = cb + (size_t)warp * C_DIM;
    float s = 0.0f, mx = 0.0f;
#pragma unroll
    for (int t = 0; t < 8; ++t) {
        float v = p[lane + 32 * t];
        s = fmaf(v, v, s);
        mx = fmaxf(mx, fabsf(v));
    }
#pragma unroll
    for (int o = 16; o > 0; o >>= 1) {
        s += __shfl_xor_sync(0xffffffffu, s, o);
        mx = fmaxf(mx, __shfl_xor_sync(0xffffffffu, mx, o));
    }
    if (lane == 0) {
        g_e2[warp] = s;
        mx = fmaxf(mx, 1e-20f);
        g_se[warp]    = mx * (1.0f / 127.0f);
        g_seinv[warp] = 127.0f / mx;
    }
}

__global__ void quant_cb_kernel(const float* __restrict__ cb) {
    int t = blockIdx.x * 256 + threadIdx.x;
    int cc = t >> 13;
    int k  = t & 8191;
    float4 v = *(const float4*)(cb + (size_t)k * 256 + cc * 4);
    float inv = g_seinv[k];
    int w = q8(v.x, inv) | (q8(v.y, inv) << 8) |
            (q8(v.z, inv) << 16) | (q8(v.w, inv) << 24);
    g_cbT[cc][k] = w;
}

// ---------------------------------------------------------------------------
// DP4A screen (R10, validated): 112 rows x all 8192 cands (64 tiles of 128).
// 256 threads (8 warps, SMSP-balanced), 7x8 microtile, double-buffered B,
// one __syncthreads per tile, direct g_cnt/g_cand writes.
// ---------------------------------------------------------------------------
#define A_BYTES    (CHUNKS * 128 * 4)        // 32768 (padded: 16 strips x 8)
#define BBUF_BYTES (CHUNKS * 128 * 4)        // 32768
#define SE_BYTES   512u
#define DYN_SM     (A_BYTES + 2u * BBUF_BYTES + 2u * SE_BYTES)  // 99328

__global__ __launch_bounds__(NTH, 1) void screen_dp4a_kernel() {
    extern __shared__ char dsm[];
    int*   As = (int*)dsm;                                    // [64][128] padded
    int*   Bs = (int*)(dsm + A_BYTES);                        // [2][64][128]
    float* Se = (float*)(dsm + A_BYTES + 2u * BBUF_BYTES);    // [2][128]
    __shared__ unsigned s_rowmax[TM];
    __shared__ int s_cnt[TM];
    __shared__ int s_list[TM * CAP];

    const int tid = threadIdx.x;
    const int tx = tid & 15;       // 16 candidate strips
    const int ty = tid >> 4;       // 16 row strips (7 rows each)
    const int row0 = blockIdx.x * TM;
    const unsigned smu = smem_u32(dsm);

    for (int i = tid; i < TM; i += NTH) { s_cnt[i] = 0; s_rowmax[i] = 0u; }

    float margin_u[7];
#pragma unroll
    for (int i = 0; i < 7; ++i)
        margin_u[i] = MARGIN_EZ * g_szinv[min(row0 + ty * 7 + i, N_ROWS - 1)];

    // ---- B0 + Se0 via cp.async (aligned) ----
    for (int s = tid; s < CHUNKS * 32; s += NTH) {
        int cc = s & 63, u = s >> 6;
        CP_ASYNC16(smu + A_BYTES + (cc * 128 + u * 4) * 4, &g_cbT[cc][u * 4]);
    }
    if (tid < 32) CP_ASYNC16(smu + A_BYTES + 2u * BBUF_BYTES + tid * 16,
                             (const char*)g_se + tid * 16);
    CP_COMMIT();

    // ---- A preload via plain loads (once per block) ----
    for (int s = tid; s < CHUNKS * TM; s += NTH) {
        int cc = s & 63, lr = s >> 6;
        int strip = lr / 7, rr = lr - strip * 7;
        As[cc * 128 + strip * 8 + rr] = g_qzT[cc][min(row0 + lr, N_ROWS - 1)];
    }

    for (int t = 0; t < 64; ++t) {
        CP_WAIT0();
        __syncthreads();   // publishes plain A stores (t=0) and B[t]

        if (t + 1 < 64) {
            const int k1 = (t + 1) * 128;
            const int b1 = (t + 1) & 1;
            unsigned dst = smu + A_BYTES + (unsigned)b1 * BBUF_BYTES;
            for (int s = tid; s < CHUNKS * 32; s += NTH) {
                int cc = s & 63, u = s >> 6;
                CP_ASYNC16(dst + (cc * 128 + u * 4) * 4, &g_cbT[cc][k1 + u * 4]);
            }
            if (tid < 32)
                CP_ASYNC16(smu + A_BYTES + 2u * BBUF_BYTES + (unsigned)b1 * SE_BYTES + tid * 16,
                           (const char*)(g_se + k1) + tid * 16);
            CP_COMMIT();
        }

        const int*   Bt = Bs + (t & 1) * (BBUF_BYTES / 4);
        const float* St = Se + (t & 1) * 128;
        int acc[7][8];
#pragma unroll
        for (int i = 0; i < 7; ++i)
#pragma unroll
            for (int j = 0; j < 8; ++j) acc[i][j] = 0;

#pragma unroll 4
        for (int cc = 0; cc < CHUNKS; ++cc) {
            int a[8], b[8];
            *(int4*)&a[0] = *(const int4*)&As[cc * 128 + ty * 8];
            *(int4*)&a[4] = *(const int4*)&As[cc * 128 + ty * 8 + 4];   // a[7] = pad
            *(int4*)&b[0] = *(const int4*)&Bt[cc * 128 + tx * 4];
            *(int4*)&b[4] = *(const int4*)&Bt[cc * 128 + 64 + tx * 4];
#pragma unroll
            for (int i = 0; i < 7; ++i)
#pragma unroll
                for (int j = 0; j < 8; ++j)
                    acc[i][j] = __dp4a(a[i], b[j], acc[i][j]);
        }

        float sev[8];
#pragma unroll
        for (int j = 0; j < 4; ++j) {
            sev[j]     = St[tx * 4 + j];
            sev[j + 4] = St[64 + tx * 4 + j];
        }

#pragma unroll
        for (int i = 0; i < 7; ++i) {
            float m = -3.4e38f;
#pragma unroll
            for (int j = 0; j < 8; ++j) m = fmaxf(m, sev[j] * (float)acc[i][j]);
            atomicMax(&s_rowmax[ty * 7 + i], fkey(m));
        }
#pragma unroll
        for (int i = 0; i < 7; ++i) {
            const int r = ty * 7 + i;
            const float th = fdec(s_rowmax[r]) - margin_u[i];
#pragma unroll
            for (int j = 0; j < 8; ++j) {
                float v = sev[j] * (float)acc[i][j];
                if (v > th) {
                    int k = t * 128 + ((j < 4) ? (tx * 4 + j) : (64 + tx * 4 + j - 4));
                    int slot = atomicAdd(&s_cnt[r], 1);
                    if (slot < CAP) s_list[r * CAP + slot] = k;
                }
            }
        }
    }
    __syncthreads();

    for (int r = tid; r < TM; r += NTH)
        if (row0 + r < N_ROWS) g_cnt[row0 + r] = s_cnt[r];
    for (int i = tid; i < TM * CAP; i += NTH) {
        int r = i >> 5;
        if (row0 + r < N_ROWS) g_cand[(row0 + r) * CAP + (i & 31)] = s_list[i];
    }
}

// ---------------------------------------------------------------------------
// exact recheck (validated): smem-staged candidates, bit-identical dot
// ---------------------------------------------------------------------------
__global__ __launch_bounds__(32) void recheck_kernel(const float* __restrict__ cb)
{
    __shared__ float srows[256 * 33];
    __shared__ float zs[256];
    const int n = blockIdx.x;
    const int lane = threadIdx.x;

    {
        const float4* zr4 = (const float4*)(g_zrow + (size_t)n * 256);
        float4* zs4 = (float4*)zs;
        zs4[lane] = zr4[lane];
        zs4[lane + 32] = zr4[lane + 32];
    }
    __syncwarp();

    const float z2v = g_z2[n];
    const int cnt = g_cnt[n];
    unsigned long long key = ~0ull;

    if (cnt <= CAP) {
        const int myk = g_cand[n * CAP + min(lane, cnt - 1)];
        const int sub  = lane >> 3;
        const int ch   = lane & 7;
        for (int kk0 = 0; kk0 < cnt; kk0 += 4) {
            const int kk = kk0 + sub;
            const int kb2 = __shfl_sync(0xffffffffu, myk, min(kk, cnt - 1));
            const float4* cr4 = (const float4*)(cb + (size_t)kb2 * 256);
            const bool act = (kk < cnt);
#pragma unroll
            for (int u = 0; u < 8; ++u) {
                float4 v = cr4[ch + 8 * u];
                if (act) {
                    const int c = (ch + 8 * u) * 4;
                    srows[(c + 0) * 33 + kk] = v.x;
                    srows[(c + 1) * 33 + kk] = v.y;
                    srows[(c + 2) * 33 + kk] = v.z;
                    srows[(c + 3) * 33 + kk] = v.w;
                }
            }
        }
        __syncwarp();
        if (lane < cnt) {
            float a = 0.0f;
#pragma unroll 8
            for (int c = 0; c < 256; ++c)
                a = fmaf(zs[c], srows[c * 33 + lane], a);
            float d = (z2v + g_e2[myk]) - 2.0f * a;
            key = ((unsigned long long)__float_as_uint(d) << 32) | (unsigned)myk;
        }
    } else {
        for (int k = lane; k < K_CB; k += 32) {
            const float* cr = cb + (size_t)k * 256;
            float a = 0.0f;
#pragma unroll 16
            for (int c = 0; c < 256; ++c) a = fmaf(zs[c], cr[c], a);
            float d = (z2v + g_e2[k]) - 2.0f * a;
            unsigned long long kk = ((unsigned long long)__float_as_uint(d) << 32) | (unsigned)k;
            key = (kk < key) ? kk : key;
        }
    }
#pragma unroll
    for (int o = 16; o > 0; o >>= 1) {
        unsigned long long ok = __shfl_xor_sync(0xffffffffu, key, o);
        key = (ok < key) ? ok : key;
    }
    if (lane == 0) g_bestidx[n] = (int)(unsigned)(key & 0xffffffffu);
}

// ---------------------------------------------------------------------------
// epilogue: zp from g_zrow (contiguous quad -> float4 coalesced)
// ---------------------------------------------------------------------------
__global__ void epilogue_kernel(const float* __restrict__ cb,
                                float* __restrict__ out, int out_size)
{
    int q = blockIdx.x * 256 + threadIdx.x;
    int t = q * 4;
    int c2 = t & 255;
    int w2 = (t >> 8) & 31;
    int h2 = (t >> 13) & 31;
    int b  = t >> 18;
    int n = b * 1024 + w2 * 32 + (c2 >> 3);           // scrambled gather index
    int cbase = (c2 & 7) * 32 + h2;
    const float* cr = cb + (size_t)g_bestidx[n] * C_DIM + cbase;
    float4 v;
    v.x = cr[0]; v.y = cr[32]; v.z = cr[64]; v.w = cr[96];
    float4 zv = *(const float4*)(g_zrow + (size_t)(b * 1024 + h2 * 32 + w2) * 256 + c2);
    float d0 = zv.x - v.x;
    float d1 = zv.y - v.y;
    float d2 = zv.z - v.z;
    float d3 = zv.w - v.w;
    *(float4*)(out + t) = v;
    float diff2 = d0 * d0 + d1 * d1 + d2 * d2 + d3 * d3;

    __shared__ double sred[256];
    sred[threadIdx.x] = (double)diff2;
    __syncthreads();
#pragma unroll
    for (int s = 128; s > 0; s >>= 1) {
        if (threadIdx.x < s) sred[threadIdx.x] += sred[threadIdx.x + s];
        __syncthreads();
    }
    if (threadIdx.x == 0) g_losspart[blockIdx.x] = sred[0];
}

__global__ void finalize_kernel(float* __restrict__ out, int out_size)
{
    __shared__ double sred[256];
    double s = 0.0;
    for (int i = threadIdx.x; i < 4096; i += 256) s += g_losspart[i];
    sred[threadIdx.x] = s;
    __syncthreads();
#pragma unroll
    for (int st = 128; st > 0; st >>= 1) {
        if (threadIdx.x < st) sred[threadIdx.x] += sred[threadIdx.x + st];
        __syncthreads();
    }
    if (threadIdx.x == 0) {
        double m = sred[0] / (double)Z_ELEMS;
        float loss = (float)(m + 0.25 * m);
        if (OUT_LOSS_OFF < out_size) out[OUT_LOSS_OFF] = loss;
    }
    for (int i = threadIdx.x; i < N_ROWS; i += 256) {
        int o = OUT_IDX_OFF + i;
        if (o < out_size) out[o] = (float)g_bestidx[i];
    }
}

extern "C" void kernel_launch(void* const* d_in, const int* in_sizes, int n_in,
                              void* d_out, int out_size)
{
    const float* z  = (const float*)d_in[0];
    const float* cb = (const float*)d_in[1];
    float* out = (float*)d_out;

    cudaFuncSetAttribute(screen_dp4a_kernel,
                         cudaFuncAttributeMaxDynamicSharedMemorySize, DYN_SM);

    rowstat_z_kernel<<<512, 256>>>(z);
    rowstat_e_kernel<<<(K_CB * 32) / 256, 256>>>(cb);
    quant_cb_kernel<<<(CHUNKS * K_CB) / 256, 256>>>(cb);
    screen_dp4a_kernel<<<NBLK, NTH, DYN_SM>>>();
    recheck_kernel<<<N_ROWS, 32>>>(cb);
    epilogue_kernel<<<Z_ELEMS / 1024, 256>>>(cb, out, out_size);
    finalize_kernel<<<1, 256>>>(out, out_size);
}

// round 13
// speedup vs baseline: 3.4205x; 1.0097x over previous
#include <cuda_runtime.h>
#include <cuda_bf16.h>
#include <cstdint>

#define BATCH   16
#define C_DIM   256
#define N_ROWS  16384
#define K_CB    8192
#define Z_ELEMS 4194304
#define OUT_LOSS_OFF 4194304
#define OUT_IDX_OFF  4194305

#define CAP       32
#define MARGIN_EZ 2e-4f
#define CHUNKS    64            // 256 int8 = 64 packed int32 per row

#define TM        112           // rows per screen block (16 warps x 7 rows)
#define NTH       512           // 16 warps -> 4/SMSP, balanced
#define NBLK      147           // ceil(16384/112)

// ---- static device scratch ----
__device__ __align__(16) int   g_qzT[CHUNKS][N_ROWS];   // z int8, chunk-major
__device__ __align__(16) int   g_cbT[CHUNKS][K_CB];     // codebook int8, chunk-major
__device__ __align__(16) float g_zrow[N_ROWS * C_DIM];  // z fp32, row-major
__device__ float  g_z2[N_ROWS];
__device__ float  g_szinv[N_ROWS];   // 127/max|z_row|
__device__ float  g_e2[K_CB];
__device__ float  g_se[K_CB];        // max|e_k|/127
__device__ float  g_seinv[K_CB];     // 127/max|e_k|
__device__ int    g_cnt[N_ROWS];
__device__ int    g_cand[N_ROWS * CAP];
__device__ int    g_bestidx[N_ROWS];
__device__ double g_losspart[4096];

__device__ __forceinline__ unsigned fkey(float f) {
    unsigned u = __float_as_uint(f);
    return (u & 0x80000000u) ? ~u : (u | 0x80000000u);
}
__device__ __forceinline__ float fdec(unsigned k) {
    unsigned u = (k & 0x80000000u) ? (k & 0x7fffffffu) : ~k;
    return __uint_as_float(u);
}
__device__ __forceinline__ uint32_t smem_u32(const void* p) {
    uint32_t a;
    asm("{ .reg .u64 t; cvta.to.shared.u64 t, %1; cvt.u32.u64 %0, t; }" : "=r"(a) : "l"(p));
    return a;
}
__device__ __forceinline__ int q8(float v, float inv) {
    int q = __float2int_rn(v * inv);
    q = max(-127, min(127, q));
    return q & 255;
}
#define CP_ASYNC16(dst, src) \
    asm volatile("cp.async.cg.shared.global [%0],[%1],16;\n" :: "r"(dst), "l"(src))
#define CP_COMMIT() asm volatile("cp.async.commit_group;\n")
#define CP_WAIT0()  asm volatile("cp.async.wait_group 0;\n")

// ---------------------------------------------------------------------------
// rowstat_z: coalesced load; z2 bit-identical to R1; emits g_zrow AND g_qzT.
// ---------------------------------------------------------------------------
__global__ __launch_bounds__(256) void rowstat_z_kernel(const float* __restrict__ z) {
    __shared__ float sm[256 * 33];
    __shared__ float sh_inv[32];
    const int n0 = blockIdx.x * 32;
    const int b = n0 >> 10;
    const int r0 = n0 & 1023;
    const int lane = threadIdx.x & 31;
    const int w = threadIdx.x >> 5;

    for (int c = w; c < 256; c += 8)
        sm[c * 33 + lane] = z[(size_t)b * 262144 + (size_t)c * 1024 + r0 + lane];
    __syncthreads();

#pragma unroll
    for (int q = 0; q < 4; ++q) {
        const int rr = w + q * 8;
        float s = 0.0f, mx = 0.0f;
#pragma unroll
        for (int t = 0; t < 8; ++t) {
            float v = sm[(lane + 32 * t) * 33 + rr];
            s = fmaf(v, v, s);
            mx = fmaxf(mx, fabsf(v));
            g_zrow[(size_t)(n0 + rr) * 256 + lane + 32 * t] = v;
        }
#pragma unroll
        for (int o = 16; o > 0; o >>= 1) {
            s += __shfl_xor_sync(0xffffffffu, s, o);
            mx = fmaxf(mx, __shfl_xor_sync(0xffffffffu, mx, o));
        }
        if (lane == 0) {
            g_z2[n0 + rr] = s;
            float inv = 127.0f / fmaxf(mx, 1e-20f);
            g_szinv[n0 + rr] = inv;
            sh_inv[rr] = inv;
        }
    }
    __syncthreads();

#pragma unroll
    for (int i = 0; i < 8; ++i) {
        int sidx = threadIdx.x + 256 * i;      // 0..2047
        int rr = sidx & 31, cc = sidx >> 5;
        float inv = sh_inv[rr];
        int wq = q8(sm[(4 * cc + 0) * 33 + rr], inv)
               | (q8(sm[(4 * cc + 1) * 33 + rr], inv) << 8)
               | (q8(sm[(4 * cc + 2) * 33 + rr], inv) << 16)
               | (q8(sm[(4 * cc + 3) * 33 + rr], inv) << 24);
        g_qzT[cc][n0 + rr] = wq;
    }
}

__global__ void rowstat_e_kernel(const float* __restrict__ cb) {
    int warp = (blockIdx.x * blockDim.x + threadIdx.x) >> 5;
    int lane = threadIdx.x & 31;
    if (warp >= K_CB) return;
    const float* p = cb + (size_t)warp * C_DIM;
    float s = 0.0f, mx = 0.0f;
#pragma unroll
    for (int t = 0; t < 8; ++t) {
        float v = p[lane + 32 * t];
        s = fmaf(v, v, s);
        mx = fmaxf(mx, fabsf(v));
    }
#pragma unroll
    for (int o = 16; o > 0; o >>= 1) {
        s += __shfl_xor_sync(0xffffffffu, s, o);
        mx = fmaxf(mx, __shfl_xor_sync(0xffffffffu, mx, o));
    }
    if (lane == 0) {
        g_e2[warp] = s;
        mx = fmaxf(mx, 1e-20f);
        g_se[warp]    = mx * (1.0f / 127.0f);
        g_seinv[warp] = 127.0f / mx;
    }
}

__global__ void quant_cb_kernel(const float* __restrict__ cb) {
    int t = blockIdx.x * 256 + threadIdx.x;
    int cc = t >> 13;
    int k  = t & 8191;
    float4 v = *(const float4*)(cb + (size_t)k * 256 + cc * 4);
    float inv = g_seinv[k];
    int w = q8(v.x, inv) | (q8(v.y, inv) << 8) |
            (q8(v.z, inv) << 16) | (q8(v.w, inv) << 24);
    g_cbT[cc][k] = w;
}

// ---------------------------------------------------------------------------
// DP4A screen: 112 rows x 8192 cands (64 tiles of 128). 512 threads
// (16 warps, 4/SMSP), 7x4 microtile (warp = one 7-row group x 128 cands).
// Rowmax via shfl butterfly + single atomicMax per row per warp.
// ---------------------------------------------------------------------------
#define A_BYTES    (CHUNKS * 128 * 4)        // 32768 (padded: 16 strips x 8)
#define BBUF_BYTES (CHUNKS * 128 * 4)        // 32768
#define SE_BYTES   512u
#define DYN_SM     (A_BYTES + 2u * BBUF_BYTES + 2u * SE_BYTES)  // 99328

__global__ __launch_bounds__(NTH, 1) void screen_dp4a_kernel() {
    extern __shared__ char dsm[];
    int*   As = (int*)dsm;                                    // [64][128] padded
    int*   Bs = (int*)(dsm + A_BYTES);                        // [2][64][128]
    float* Se = (float*)(dsm + A_BYTES + 2u * BBUF_BYTES);    // [2][128]
    __shared__ unsigned s_rowmax[TM];
    __shared__ int s_cnt[TM];
    __shared__ int s_list[TM * CAP];

    const int tid = threadIdx.x;
    const int tx = tid & 31;       // 32 candidate strips (4 cands each)
    const int ty = tid >> 5;       // 16 warps = 16 row strips (7 rows each)
    const int row0 = blockIdx.x * TM;
    const unsigned smu = smem_u32(dsm);

    for (int i = tid; i < TM; i += NTH) { s_cnt[i] = 0; s_rowmax[i] = 0u; }

    float margin_u[7];
#pragma unroll
    for (int i = 0; i < 7; ++i)
        margin_u[i] = MARGIN_EZ * g_szinv[min(row0 + ty * 7 + i, N_ROWS - 1)];

    // ---- B0 + Se0 via cp.async (aligned) ----
    for (int s = tid; s < CHUNKS * 32; s += NTH) {
        int cc = s & 63, u = s >> 6;
        CP_ASYNC16(smu + A_BYTES + (cc * 128 + u * 4) * 4, &g_cbT[cc][u * 4]);
    }
    if (tid < 32) CP_ASYNC16(smu + A_BYTES + 2u * BBUF_BYTES + tid * 16,
                             (const char*)g_se + tid * 16);
    CP_COMMIT();

    // ---- A preload via plain loads (once per block) ----
    for (int s = tid; s < CHUNKS * TM; s += NTH) {
        int cc = s & 63, lr = s >> 6;
        int strip = lr / 7, rr = lr - strip * 7;
        As[cc * 128 + strip * 8 + rr] = g_qzT[cc][min(row0 + lr, N_ROWS - 1)];
    }

    for (int t = 0; t < 64; ++t) {
        CP_WAIT0();
        __syncthreads();   // publishes plain A stores (t=0) and B[t]

        if (t + 1 < 64) {
            const int k1 = (t + 1) * 128;
            const int b1 = (t + 1) & 1;
            unsigned dst = smu + A_BYTES + (unsigned)b1 * BBUF_BYTES;
            for (int s = tid; s < CHUNKS * 32; s += NTH) {
                int cc = s & 63, u = s >> 6;
                CP_ASYNC16(dst + (cc * 128 + u * 4) * 4, &g_cbT[cc][k1 + u * 4]);
            }
            if (tid < 32)
                CP_ASYNC16(smu + A_BYTES + 2u * BBUF_BYTES + (unsigned)b1 * SE_BYTES + tid * 16,
                           (const char*)(g_se + k1) + tid * 16);
            CP_COMMIT();
        }

        const int*   Bt = Bs + (t & 1) * (BBUF_BYTES / 4);
        const float* St = Se + (t & 1) * 128;
        int acc[7][4];
#pragma unroll
        for (int i = 0; i < 7; ++i)
#pragma unroll
            for (int j = 0; j < 4; ++j) acc[i][j] = 0;

#pragma unroll 8
        for (int cc = 0; cc < CHUNKS; ++cc) {
            int a[8], b[4];
            *(int4*)&a[0] = *(const int4*)&As[cc * 128 + ty * 8];
            *(int4*)&a[4] = *(const int4*)&As[cc * 128 + ty * 8 + 4];   // a[7] = pad
            *(int4*)&b[0] = *(const int4*)&Bt[cc * 128 + tx * 4];
#pragma unroll
            for (int i = 0; i < 7; ++i)
#pragma unroll
                for (int j = 0; j < 4; ++j)
                    acc[i][j] = __dp4a(a[i], b[j], acc[i][j]);
        }

        float sev[4];
#pragma unroll
        for (int j = 0; j < 4; ++j) sev[j] = St[tx * 4 + j];

        // per-row warp max (all 32 lanes of this warp own the same 7 rows)
#pragma unroll
        for (int i = 0; i < 7; ++i) {
            float m = -3.4e38f;
#pragma unroll
            for (int j = 0; j < 4; ++j) m = fmaxf(m, sev[j] * (float)acc[i][j]);
#pragma unroll
            for (int o = 16; o > 0; o >>= 1)
                m = fmaxf(m, __shfl_xor_sync(0xffffffffu, m, o));
            if (tx == 0) atomicMax(&s_rowmax[ty * 7 + i], fkey(m));
        }
        // append pass (relaxed rowmax read: stale -> lower threshold -> safe)
#pragma unroll
        for (int i = 0; i < 7; ++i) {
            const int r = ty * 7 + i;
            const float th = fdec(s_rowmax[r]) - margin_u[i];
#pragma unroll
            for (int j = 0; j < 4; ++j) {
                float v = sev[j] * (float)acc[i][j];
                if (v > th) {
                    int k = t * 128 + tx * 4 + j;
                    int slot = atomicAdd(&s_cnt[r], 1);
                    if (slot < CAP) s_list[r * CAP + slot] = k;
                }
            }
        }
    }
    __syncthreads();

    for (int r = tid; r < TM; r += NTH)
        if (row0 + r < N_ROWS) g_cnt[row0 + r] = s_cnt[r];
    for (int i = tid; i < TM * CAP; i += NTH) {
        int r = i >> 5;
        if (row0 + r < N_ROWS) g_cand[(row0 + r) * CAP + (i & 31)] = s_list[i];
    }
}

// ---------------------------------------------------------------------------
// exact recheck (validated): smem-staged candidates, bit-identical dot
// ---------------------------------------------------------------------------
__global__ __launch_bounds__(32) void recheck_kernel(const float* __restrict__ cb)
{
    __shared__ float srows[256 * 33];
    __shared__ float zs[256];
    const int n = blockIdx.x;
    const int lane = threadIdx.x;

    {
        const float4* zr4 = (const float4*)(g_zrow + (size_t)n * 256);
        float4* zs4 = (float4*)zs;
        zs4[lane] = zr4[lane];
        zs4[lane + 32] = zr4[lane + 32];
    }
    __syncwarp();

    const float z2v = g_z2[n];
    const int cnt = g_cnt[n];
    unsigned long long key = ~0ull;

    if (cnt <= CAP) {
        const int myk = g_cand[n * CAP + min(lane, cnt - 1)];
        const int sub  = lane >> 3;
        const int ch   = lane & 7;
        for (int kk0 = 0; kk0 < cnt; kk0 += 4) {
            const int kk = kk0 + sub;
            const int kb2 = __shfl_sync(0xffffffffu, myk, min(kk, cnt - 1));
            const float4* cr4 = (const float4*)(cb + (size_t)kb2 * 256);
            const bool act = (kk < cnt);
#pragma unroll
            for (int u = 0; u < 8; ++u) {
                float4 v = cr4[ch + 8 * u];
                if (act) {
                    const int c = (ch + 8 * u) * 4;
                    srows[(c + 0) * 33 + kk] = v.x;
                    srows[(c + 1) * 33 + kk] = v.y;
                    srows[(c + 2) * 33 + kk] = v.z;
                    srows[(c + 3) * 33 + kk] = v.w;
                }
            }
        }
        __syncwarp();
        if (lane < cnt) {
            float a = 0.0f;
#pragma unroll 8
            for (int c = 0; c < 256; ++c)
                a = fmaf(zs[c], srows[c * 33 + lane], a);
            float d = (z2v + g_e2[myk]) - 2.0f * a;
            key = ((unsigned long long)__float_as_uint(d) << 32) | (unsigned)myk;
        }
    } else {
        for (int k = lane; k < K_CB; k += 32) {
            const float* cr = cb + (size_t)k * 256;
            float a = 0.0f;
#pragma unroll 16
            for (int c = 0; c < 256; ++c) a = fmaf(zs[c], cr[c], a);
            float d = (z2v + g_e2[k]) - 2.0f * a;
            unsigned long long kk = ((unsigned long long)__float_as_uint(d) << 32) | (unsigned)k;
            key = (kk < key) ? kk : key;
        }
    }
#pragma unroll
    for (int o = 16; o > 0; o >>= 1) {
        unsigned long long ok = __shfl_xor_sync(0xffffffffu, key, o);
        key = (ok < key) ? ok : key;
    }
    if (lane == 0) g_bestidx[n] = (int)(unsigned)(key & 0xffffffffu);
}

// ---------------------------------------------------------------------------
// epilogue: zp from g_zrow (contiguous quad -> float4 coalesced)
// ---------------------------------------------------------------------------
__global__ void epilogue_kernel(const float* __restrict__ cb,
                                float* __restrict__ out, int out_size)
{
    int q = blockIdx.x * 256 + threadIdx.x;
    int t = q * 4;
    int c2 = t & 255;
    int w2 = (t >> 8) & 31;
    int h2 = (t >> 13) & 31;
    int b  = t >> 18;
    int n = b * 1024 + w2 * 32 + (c2 >> 3);           // scrambled gather index
    int cbase = (c2 & 7) * 32 + h2;
    const float* cr = cb + (size_t)g_bestidx[n] * C_DIM + cbase;
    float4 v;
    v.x = cr[0]; v.y = cr[32]; v.z = cr[64]; v.w = cr[96];
    float4 zv = *(const float4*)(g_zrow + (size_t)(b * 1024 + h2 * 32 + w2) * 256 + c2);
    float d0 = zv.x - v.x;
    float d1 = zv.y - v.y;
    float d2 = zv.z - v.z;
    float d3 = zv.w - v.w;
    *(float4*)(out + t) = v;
    float diff2 = d0 * d0 + d1 * d1 + d2 * d2 + d3 * d3;

    __shared__ double sred[256];
    sred[threadIdx.x] = (double)diff2;
    __syncthreads();
#pragma unroll
    for (int s = 128; s > 0; s >>= 1) {
        if (threadIdx.x < s) sred[threadIdx.x] += sred[threadIdx.x + s];
        __syncthreads();
    }
    if (threadIdx.x == 0) g_losspart[blockIdx.x] = sred[0];
}

__global__ void finalize_kernel(float* __restrict__ out, int out_size)
{
    __shared__ double sred[256];
    double s = 0.0;
    for (int i = threadIdx.x; i < 4096; i += 256) s += g_losspart[i];
    sred[threadIdx.x] = s;
    __syncthreads();
#pragma unroll
    for (int st = 128; st > 0; st >>= 1) {
        if (threadIdx.x < st) sred[threadIdx.x] += sred[threadIdx.x + st];
        __syncthreads();
    }
    if (threadIdx.x == 0) {
        double m = sred[0] / (double)Z_ELEMS;
        float loss = (float)(m + 0.25 * m);
        if (OUT_LOSS_OFF < out_size) out[OUT_LOSS_OFF] = loss;
    }
    for (int i = threadIdx.x; i < N_ROWS; i += 256) {
        int o = OUT_IDX_OFF + i;
        if (o < out_size) out[o] = (float)g_bestidx[i];
    }
}

extern "C" void kernel_launch(void* const* d_in, const int* in_sizes, int n_in,
                              void* d_out, int out_size)
{
    const float* z  = (const float*)d_in[0];
    const float* cb = (const float*)d_in[1];
    float* out = (float*)d_out;

    cudaFuncSetAttribute(screen_dp4a_kernel,
                         cudaFuncAttributeMaxDynamicSharedMemorySize, DYN_SM);

    rowstat_z_kernel<<<512, 256>>>(z);
    rowstat_e_kernel<<<(K_CB * 32) / 256, 256>>>(cb);
    quant_cb_kernel<<<(CHUNKS * K_CB) / 256, 256>>>(cb);
    screen_dp4a_kernel<<<NBLK, NTH, DYN_SM>>>();
    recheck_kernel<<<N_ROWS, 32>>>(cb);
    epilogue_kernel<<<Z_ELEMS / 1024, 256>>>(cb, out, out_size);
    finalize_kernel<<<1, 256>>>(out, out_size);
}